// round 13
// baseline (speedup 1.0000x reference)
#include <cuda_runtime.h>
#include <cuda_fp16.h>
#include <stdint.h>

#define C_     128
#define HH     112
#define WW     112
#define BATCH  8
#define TABW   512            // 511 valid entries + 1 pad (255 = zero-pixel)
#define NTHR   128            // 4 warps; warp = 14 out rows; lane<28 = 4 cols
#define HROWS  56             // rows per block (half channel)

// Per-channel packed tables:
// g_tab8[c*512+i] = half8 {t00,t01,t02,t10,t11,t12,t20,t21} for index i
// g_tab1[c*512+i] = float t22
__device__ uint4 g_tab8[C_ * TABW];
__device__ float g_tab1[C_ * TABW];

__global__ void build_table_kernel(const float* __restrict__ weight,
                                   const float* __restrict__ lut) {
    int c = blockIdx.x;
    int j = threadIdx.x;             // 512 threads, one entry each

    float v[9];
    #pragma unroll
    for (int k = 0; k < 9; k++) {
        float w  = weight[c * 9 + k];
        float t1 = rintf(w * 1000.0f);
        t1 = fminf(fmaxf(t1, -255.0f), 255.0f);
        int   i1 = (int)fabsf(t1);
        float s1 = (t1 > 0.0f) ? 1.0f : ((t1 < 0.0f) ? -1.0f : 0.0f);
        float val = 0.0f;
        if (j < 511) {
            int t2 = j - 255;
            int i2 = abs(t2);
            bool pos = (s1 > 0.0f && t2 > 0) || (s1 < 0.0f && t2 < 0);
            val = lut[i1 * 256 + i2] * (pos ? 1.0f : -1.0f) * (1.0f / 1000.0f);
        }
        v[k] = val;
    }
    __half2 p0 = __floats2half2_rn(v[0], v[1]);
    __half2 p1 = __floats2half2_rn(v[2], v[3]);
    __half2 p2 = __floats2half2_rn(v[4], v[5]);
    __half2 p3 = __floats2half2_rn(v[6], v[7]);
    uint4 q;
    q.x = *reinterpret_cast<uint32_t*>(&p0);
    q.y = *reinterpret_cast<uint32_t*>(&p1);
    q.z = *reinterpret_cast<uint32_t*>(&p2);
    q.w = *reinterpret_cast<uint32_t*>(&p3);
    g_tab8[(size_t)c * TABW + j] = q;
    g_tab1[(size_t)c * TABW + j] = v[8];
}

__device__ __forceinline__ float h_lo(uint32_t u) {
    __half2 h = *reinterpret_cast<__half2*>(&u);
    return __low2float(h);
}
__device__ __forceinline__ float h_hi(uint32_t u) {
    __half2 h = *reinterpret_cast<__half2*>(&u);
    return __high2float(h);
}

__device__ __forceinline__ float4 ldrow(const float* __restrict__ xp, int r, int col, bool act) {
    if (act && r >= 0 && r < HH)
        return *(const float4*)(xp + r * WW + col);
    return make_float4(0.0f, 0.0f, 0.0f, 0.0f);
}

// One idx row z: 4 LDS.128 + 4 LDS.32 gathers, halos via value-shuffle.
// Yields three 4-wide partial rows: P0 -> out z+1, P1 -> out z, P2 -> out z-1.
__device__ __forceinline__ void proc_row(const uint4* __restrict__ tab8,
                                         const float* __restrict__ tab1,
                                         uint4 g_pad, int lane, float4 f,
                                         float4& P0, float4& P1, float4& P2) {
    int i0 = min(max(__float2int_rn(f.x), -255), 255) + 255;
    int i1 = min(max(__float2int_rn(f.y), -255), 255) + 255;
    int i2 = min(max(__float2int_rn(f.z), -255), 255) + 255;
    int i3 = min(max(__float2int_rn(f.w), -255), 255) + 255;

    // hr index (right halo) for the t22 scalar gather.
    uint32_t hr = (uint32_t)__shfl_down_sync(0xffffffffu, i0, 1);
    // lane 27's source (lane 28) quantized a zero row -> 255 (pad). OK.

    uint4 g1 = tab8[i0], g2 = tab8[i1], g3 = tab8[i2], g4 = tab8[i3];
    float f0 = tab1[i1], f1 = tab1[i2], f2 = tab1[i3], f3 = tab1[hr];

    // Left halo entry g0 = left lane's g4 (3 words needed).
    uint32_t s4x = __shfl_up_sync(0xffffffffu, g4.x, 1);
    uint32_t s4y = __shfl_up_sync(0xffffffffu, g4.y, 1);
    uint32_t s4w = __shfl_up_sync(0xffffffffu, g4.w, 1);
    if (lane == 0) { s4x = g_pad.x; s4y = g_pad.y; s4w = g_pad.w; }
    // Right halo entry g5 = right lane's g1 (2 words needed).
    uint32_t s1y = __shfl_down_sync(0xffffffffu, g1.y, 1);
    uint32_t s1z = __shfl_down_sync(0xffffffffu, g1.z, 1);
    // lane 27 receives lane 28's pad gathers (idx 255). OK.

    P0.x = h_lo(s4x)  + h_hi(g1.x) + h_lo(g2.y);
    P0.y = h_lo(g1.x) + h_hi(g2.x) + h_lo(g3.y);
    P0.z = h_lo(g2.x) + h_hi(g3.x) + h_lo(g4.y);
    P0.w = h_lo(g3.x) + h_hi(g4.x) + h_lo(s1y);

    P1.x = h_hi(s4y)  + h_lo(g1.z) + h_hi(g2.z);
    P1.y = h_hi(g1.y) + h_lo(g2.z) + h_hi(g3.z);
    P1.z = h_hi(g2.y) + h_lo(g3.z) + h_hi(g4.z);
    P1.w = h_hi(g3.y) + h_lo(g4.z) + h_hi(s1z);

    P2.x = h_lo(s4w)  + h_hi(g1.w) + f0;
    P2.y = h_lo(g1.w) + h_hi(g2.w) + f1;
    P2.z = h_lo(g2.w) + h_hi(g3.w) + f2;
    P2.w = h_lo(g3.w) + h_hi(g4.w) + f3;
}

__global__ __launch_bounds__(NTHR, 16) void conv_kernel(const float* __restrict__ x,
                                                        float* __restrict__ out) {
    __shared__ uint4 tab8[TABW];                 // 8192 B
    __shared__ float tab1[TABW];                 // 2048 B

    int bid  = blockIdx.x;                 // (b, c, half)
    int half = bid & 1;
    int c    = (bid >> 1) & (C_ - 1);
    int b    = bid >> 8;
    int t    = threadIdx.x;

    // Stage this channel's tables once.
    {
        const uint4* ts = g_tab8 + (size_t)c * TABW;
        const float* fs = g_tab1 + (size_t)c * TABW;
        #pragma unroll
        for (int i = t; i < TABW; i += NTHR) {
            tab8[i] = ts[i];
            tab1[i] = fs[i];
        }
    }
    __syncthreads();

    int warp = t >> 5;
    int lane = t & 31;
    bool act = lane < 28;
    int col  = 4 * lane;
    int rb   = half * HROWS + warp * 14;   // 4 warps x 14 rows = 56 per block

    const float* xp = x + ((size_t)(b * C_ + c)) * (HH * WW);
    float* obase    = out + ((size_t)(b * C_ + c)) * (HH * WW);

    uint4 g_pad = tab8[255];               // zero-pixel entry (uniform)

    float4 P0, P1, P2;
    float4 accA = make_float4(0.f, 0.f, 0.f, 0.f);
    float4 accB = make_float4(0.f, 0.f, 0.f, 0.f);

    float4 fcur  = ldrow(xp, rb - 1, col, act);
    float4 fnext = ldrow(xp, rb, col, act);

    // Peel z = rb-1: accB = P0.
    proc_row(tab8, tab1, g_pad, lane, fcur, P0, P1, P2);
    accB = P0;

    // Peel z = rb: accA = accB + P1; accB = P0. (out[rb-1] not ours)
    fcur = fnext;
    fnext = ldrow(xp, rb + 1, col, act);
    proc_row(tab8, tab1, g_pad, lane, fcur, P0, P1, P2);
    accA.x = accB.x + P1.x; accA.y = accB.y + P1.y;
    accA.z = accB.z + P1.z; accA.w = accB.w + P1.w;
    accB = P0;

    float* op = obase + rb * WW + col;

    #pragma unroll 2
    for (int i = 0; i < 14; i++) {
        // z = rb+1+i arrives; emit out row rb+i.
        fcur = fnext;
        fnext = ldrow(xp, rb + 2 + i, col, act);
        proc_row(tab8, tab1, g_pad, lane, fcur, P0, P1, P2);

        if (act) {
            float4 o;
            o.x = accA.x + P2.x;
            o.y = accA.y + P2.y;
            o.z = accA.z + P2.z;
            o.w = accA.w + P2.w;
            *(float4*)op = o;
        }
        op += WW;

        accA.x = accB.x + P1.x; accA.y = accB.y + P1.y;
        accA.z = accB.z + P1.z; accA.w = accB.w + P1.w;
        accB = P0;
    }
}

extern "C" void kernel_launch(void* const* d_in, const int* in_sizes, int n_in,
                              void* d_out, int out_size) {
    const float* x      = (const float*)d_in[0];
    const float* weight = (const float*)d_in[1];
    const float* lut    = (const float*)d_in[2];
    float* out          = (float*)d_out;

    build_table_kernel<<<C_, TABW>>>(weight, lut);
    conv_kernel<<<BATCH * C_ * 2, NTHR>>>(x, out);
}

// round 14
// speedup vs baseline: 1.1468x; 1.1468x over previous
#include <cuda_runtime.h>
#include <cuda_fp16.h>
#include <stdint.h>

#define C_     128
#define HH     112
#define WW     112
#define BATCH  8
#define TABW   512            // 511 valid entries + 1 pad (255 = zero-pixel)
#define NTHR   128            // 4 warps; warp = 14 out rows; lane<28 = 4 cols
#define HROWS  56             // rows per block (half channel)

// Per-channel packed tables:
// g_tab8[c*512+i] = half8 {t00,t01,t02,t10,t11,t12,t20,t21} for index i
// g_tab1[c*512+i] = float t22
__device__ uint4 g_tab8[C_ * TABW];
__device__ float g_tab1[C_ * TABW];

__global__ void build_table_kernel(const float* __restrict__ weight,
                                   const float* __restrict__ lut) {
    int c = blockIdx.x;
    int j = threadIdx.x;             // 512 threads, one entry each

    float v[9];
    #pragma unroll
    for (int k = 0; k < 9; k++) {
        float w  = weight[c * 9 + k];
        float t1 = rintf(w * 1000.0f);
        t1 = fminf(fmaxf(t1, -255.0f), 255.0f);
        int   i1 = (int)fabsf(t1);
        float s1 = (t1 > 0.0f) ? 1.0f : ((t1 < 0.0f) ? -1.0f : 0.0f);
        float val = 0.0f;
        if (j < 511) {
            int t2 = j - 255;
            int i2 = abs(t2);
            bool pos = (s1 > 0.0f && t2 > 0) || (s1 < 0.0f && t2 < 0);
            val = lut[i1 * 256 + i2] * (pos ? 1.0f : -1.0f) * (1.0f / 1000.0f);
        }
        v[k] = val;
    }
    __half2 p0 = __floats2half2_rn(v[0], v[1]);
    __half2 p1 = __floats2half2_rn(v[2], v[3]);
    __half2 p2 = __floats2half2_rn(v[4], v[5]);
    __half2 p3 = __floats2half2_rn(v[6], v[7]);
    uint4 q;
    q.x = *reinterpret_cast<uint32_t*>(&p0);
    q.y = *reinterpret_cast<uint32_t*>(&p1);
    q.z = *reinterpret_cast<uint32_t*>(&p2);
    q.w = *reinterpret_cast<uint32_t*>(&p3);
    g_tab8[(size_t)c * TABW + j] = q;
    g_tab1[(size_t)c * TABW + j] = v[8];
}

__device__ __forceinline__ float h_lo(uint32_t u) {
    __half2 h = *reinterpret_cast<__half2*>(&u);
    return __low2float(h);
}
__device__ __forceinline__ float h_hi(uint32_t u) {
    __half2 h = *reinterpret_cast<__half2*>(&u);
    return __high2float(h);
}

__device__ __forceinline__ float4 ldrow(const float* __restrict__ xp, int r, int col, bool act) {
    if (act && r >= 0 && r < HH)
        return *(const float4*)(xp + r * WW + col);
    return make_float4(0.0f, 0.0f, 0.0f, 0.0f);
}

// One idx row z: 4 LDS.128 + 4 LDS.32 gathers, halos via value-shuffle.
// Yields three 4-wide partial rows: P0 -> out z+1, P1 -> out z, P2 -> out z-1.
__device__ __forceinline__ void proc_row(const uint4* __restrict__ tab8,
                                         const float* __restrict__ tab1,
                                         uint32_t padx, uint32_t pady, uint32_t padw,
                                         int lane, float4 f,
                                         float4& P0, float4& P1, float4& P2) {
    int i0 = min(max(__float2int_rn(f.x), -255), 255) + 255;
    int i1 = min(max(__float2int_rn(f.y), -255), 255) + 255;
    int i2 = min(max(__float2int_rn(f.z), -255), 255) + 255;
    int i3 = min(max(__float2int_rn(f.w), -255), 255) + 255;

    uint4 g1 = tab8[i0], g2 = tab8[i1], g3 = tab8[i2], g4 = tab8[i3];
    float fz0 = tab1[i0], f0 = tab1[i1], f1 = tab1[i2], f2 = tab1[i3];
    // Right-halo t22 value = right lane's tab1[i0] (lane 28 holds pad value).
    float f3 = __shfl_down_sync(0xffffffffu, fz0, 1);

    // Left halo entry g0 = left lane's g4 (3 words needed).
    uint32_t s4x = __shfl_up_sync(0xffffffffu, g4.x, 1);
    uint32_t s4y = __shfl_up_sync(0xffffffffu, g4.y, 1);
    uint32_t s4w = __shfl_up_sync(0xffffffffu, g4.w, 1);
    if (lane == 0) { s4x = padx; s4y = pady; s4w = padw; }
    // Right halo entry g5 = right lane's g1 (2 words needed).
    uint32_t s1y = __shfl_down_sync(0xffffffffu, g1.y, 1);
    uint32_t s1z = __shfl_down_sync(0xffffffffu, g1.z, 1);
    // lane 27 receives lane 28's pad gathers (idx 255). OK.

    P0.x = h_lo(s4x)  + h_hi(g1.x) + h_lo(g2.y);
    P0.y = h_lo(g1.x) + h_hi(g2.x) + h_lo(g3.y);
    P0.z = h_lo(g2.x) + h_hi(g3.x) + h_lo(g4.y);
    P0.w = h_lo(g3.x) + h_hi(g4.x) + h_lo(s1y);

    P1.x = h_hi(s4y)  + h_lo(g1.z) + h_hi(g2.z);
    P1.y = h_hi(g1.y) + h_lo(g2.z) + h_hi(g3.z);
    P1.z = h_hi(g2.y) + h_lo(g3.z) + h_hi(g4.z);
    P1.w = h_hi(g3.y) + h_lo(g4.z) + h_hi(s1z);

    P2.x = h_lo(s4w)  + h_hi(g1.w) + f0;
    P2.y = h_lo(g1.w) + h_hi(g2.w) + f1;
    P2.z = h_lo(g2.w) + h_hi(g3.w) + f2;
    P2.w = h_lo(g3.w) + h_hi(g4.w) + f3;
}

__global__ __launch_bounds__(NTHR, 14) void conv_kernel(const float* __restrict__ x,
                                                        float* __restrict__ out) {
    __shared__ uint4 tab8[TABW];                 // 8192 B
    __shared__ float tab1[TABW];                 // 2048 B

    int bid  = blockIdx.x;                 // (b, c, half)
    int half = bid & 1;
    int c    = (bid >> 1) & (C_ - 1);
    int b    = bid >> 8;
    int t    = threadIdx.x;

    // Stage this channel's tables once.
    {
        const uint4* ts = g_tab8 + (size_t)c * TABW;
        const float* fs = g_tab1 + (size_t)c * TABW;
        #pragma unroll
        for (int i = t; i < TABW; i += NTHR) {
            tab8[i] = ts[i];
            tab1[i] = fs[i];
        }
    }
    __syncthreads();

    int warp = t >> 5;
    int lane = t & 31;
    bool act = lane < 28;
    int col  = 4 * lane;
    int rb   = half * HROWS + warp * 14;   // 4 warps x 14 rows = 56 per block

    const float* xp = x + ((size_t)(b * C_ + c)) * (HH * WW);
    float* obase    = out + ((size_t)(b * C_ + c)) * (HH * WW);

    uint32_t padx, pady, padw;             // zero-pixel entry words (uniform)
    { uint4 gp = tab8[255]; padx = gp.x; pady = gp.y; padw = gp.w; }

    float4 P0, P1, P2;
    float4 accA = make_float4(0.f, 0.f, 0.f, 0.f);
    float4 accB = make_float4(0.f, 0.f, 0.f, 0.f);

    // Peel z = rb-1: accB = P0.
    proc_row(tab8, tab1, padx, pady, padw, lane,
             ldrow(xp, rb - 1, col, act), P0, P1, P2);
    accB = P0;

    float4 fnext = ldrow(xp, rb, col, act);

    // Peel z = rb: accA = accB + P1; accB = P0. (out[rb-1] not ours)
    {
        float4 fc = fnext;
        fnext = ldrow(xp, rb + 1, col, act);
        proc_row(tab8, tab1, padx, pady, padw, lane, fc, P0, P1, P2);
    }
    accA.x = accB.x + P1.x; accA.y = accB.y + P1.y;
    accA.z = accB.z + P1.z; accA.w = accB.w + P1.w;
    accB = P0;

    float* op = obase + rb * WW + col;

    #pragma unroll 7
    for (int i = 0; i < 14; i++) {
        // z = rb+1+i arrives; emit out row rb+i.
        float4 fc = fnext;
        fnext = ldrow(xp, rb + 2 + i, col, act);
        proc_row(tab8, tab1, padx, pady, padw, lane, fc, P0, P1, P2);

        if (act) {
            float4 o;
            o.x = accA.x + P2.x;
            o.y = accA.y + P2.y;
            o.z = accA.z + P2.z;
            o.w = accA.w + P2.w;
            *(float4*)op = o;
        }
        op += WW;

        accA.x = accB.x + P1.x; accA.y = accB.y + P1.y;
        accA.z = accB.z + P1.z; accA.w = accB.w + P1.w;
        accB = P0;
    }
}

extern "C" void kernel_launch(void* const* d_in, const int* in_sizes, int n_in,
                              void* d_out, int out_size) {
    const float* x      = (const float*)d_in[0];
    const float* weight = (const float*)d_in[1];
    const float* lut    = (const float*)d_in[2];
    float* out          = (float*)d_out;

    build_table_kernel<<<C_, TABW>>>(weight, lut);
    conv_kernel<<<BATCH * C_ * 2, NTHR>>>(x, out);
}

// round 15
// speedup vs baseline: 1.3014x; 1.1348x over previous
#include <cuda_runtime.h>
#include <cuda_fp16.h>
#include <stdint.h>

#define C_     128
#define HH     112
#define WW     112
#define BATCH  8
#define TABW   512            // 511 valid entries + 1 pad (255 = zero-pixel)
#define NTHR   128            // 4 warps; warp = 14 out rows; lane<28 = 4 cols
#define HROWS  56             // rows per block (half channel)

// Per-channel packed tables:
// g_tab8[c*512+i] = half8 {t00,t01,t02,t10,t11,t12,t20,t21} for index i
// g_tab1[c*512+i] = float t22
__device__ uint4 g_tab8[C_ * TABW];
__device__ float g_tab1[C_ * TABW];

__global__ void build_table_kernel(const float* __restrict__ weight,
                                   const float* __restrict__ lut) {
    int c = blockIdx.x;
    int j = threadIdx.x;             // 512 threads, one entry each

    float v[9];
    #pragma unroll
    for (int k = 0; k < 9; k++) {
        float w  = weight[c * 9 + k];
        float t1 = rintf(w * 1000.0f);
        t1 = fminf(fmaxf(t1, -255.0f), 255.0f);
        int   i1 = (int)fabsf(t1);
        float s1 = (t1 > 0.0f) ? 1.0f : ((t1 < 0.0f) ? -1.0f : 0.0f);
        float val = 0.0f;
        if (j < 511) {
            int t2 = j - 255;
            int i2 = abs(t2);
            bool pos = (s1 > 0.0f && t2 > 0) || (s1 < 0.0f && t2 < 0);
            val = lut[i1 * 256 + i2] * (pos ? 1.0f : -1.0f) * (1.0f / 1000.0f);
        }
        v[k] = val;
    }
    __half2 p0 = __floats2half2_rn(v[0], v[1]);
    __half2 p1 = __floats2half2_rn(v[2], v[3]);
    __half2 p2 = __floats2half2_rn(v[4], v[5]);
    __half2 p3 = __floats2half2_rn(v[6], v[7]);
    uint4 q;
    q.x = *reinterpret_cast<uint32_t*>(&p0);
    q.y = *reinterpret_cast<uint32_t*>(&p1);
    q.z = *reinterpret_cast<uint32_t*>(&p2);
    q.w = *reinterpret_cast<uint32_t*>(&p3);
    g_tab8[(size_t)c * TABW + j] = q;
    g_tab1[(size_t)c * TABW + j] = v[8];
}

__device__ __forceinline__ float h_lo(uint32_t u) {
    __half2 h = *reinterpret_cast<__half2*>(&u);
    return __low2float(h);
}
__device__ __forceinline__ float h_hi(uint32_t u) {
    __half2 h = *reinterpret_cast<__half2*>(&u);
    return __high2float(h);
}

__device__ __forceinline__ float4 ldrow(const float* __restrict__ xp, int r, int col, bool act) {
    if (act && r >= 0 && r < HH)
        return *(const float4*)(xp + r * WW + col);
    return make_float4(0.0f, 0.0f, 0.0f, 0.0f);
}

// One idx row z, fused into the 3-slot accumulator ring:
//   accO += P2(z)   (out row z-1, completes)
//   accM += P1(z)   (out row z)
//   accN  = P0(z)   (out row z+1, fresh)
__device__ __forceinline__ void proc_row(const uint4* __restrict__ tab8,
                                         const float* __restrict__ tab1,
                                         uint32_t padx, uint32_t pady, uint32_t padw,
                                         int lane, float4 f,
                                         float4& accO, float4& accM, float4& accN) {
    int i0 = min(max(__float2int_rn(f.x), -255), 255) + 255;
    int i1 = min(max(__float2int_rn(f.y), -255), 255) + 255;
    int i2 = min(max(__float2int_rn(f.z), -255), 255) + 255;
    int i3 = min(max(__float2int_rn(f.w), -255), 255) + 255;

    uint4 g1 = tab8[i0], g2 = tab8[i1], g3 = tab8[i2], g4 = tab8[i3];
    float fz0 = tab1[i0], f0 = tab1[i1], f1 = tab1[i2], f2 = tab1[i3];
    // Right-halo t22 value = right lane's tab1[i0] (lane 28 holds pad value).
    float f3 = __shfl_down_sync(0xffffffffu, fz0, 1);

    // Left halo entry g0 = left lane's g4 (3 words needed).
    uint32_t s4x = __shfl_up_sync(0xffffffffu, g4.x, 1);
    uint32_t s4y = __shfl_up_sync(0xffffffffu, g4.y, 1);
    uint32_t s4w = __shfl_up_sync(0xffffffffu, g4.w, 1);
    if (lane == 0) { s4x = padx; s4y = pady; s4w = padw; }
    // Right halo entry g5 = right lane's g1 (2 words needed).
    uint32_t s1y = __shfl_down_sync(0xffffffffu, g1.y, 1);
    uint32_t s1z = __shfl_down_sync(0xffffffffu, g1.z, 1);
    // lane 27 receives lane 28's pad gathers (idx 255). OK.

    accO.x += h_lo(s4w)  + h_hi(g1.w) + f0;
    accO.y += h_lo(g1.w) + h_hi(g2.w) + f1;
    accO.z += h_lo(g2.w) + h_hi(g3.w) + f2;
    accO.w += h_lo(g3.w) + h_hi(g4.w) + f3;

    accM.x += h_hi(s4y)  + h_lo(g1.z) + h_hi(g2.z);
    accM.y += h_hi(g1.y) + h_lo(g2.z) + h_hi(g3.z);
    accM.z += h_hi(g2.y) + h_lo(g3.z) + h_hi(g4.z);
    accM.w += h_hi(g3.y) + h_lo(g4.z) + h_hi(s1z);

    accN.x = h_lo(s4x)  + h_hi(g1.x) + h_lo(g2.y);
    accN.y = h_lo(g1.x) + h_hi(g2.x) + h_lo(g3.y);
    accN.z = h_lo(g2.x) + h_hi(g3.x) + h_lo(g4.y);
    accN.w = h_lo(g3.x) + h_hi(g4.x) + h_lo(s1y);
}

__global__ __launch_bounds__(NTHR, 14) void conv_kernel(const float* __restrict__ x,
                                                        float* __restrict__ out) {
    __shared__ uint4 tab8[TABW];                 // 8192 B
    __shared__ float tab1[TABW];                 // 2048 B

    int bid  = blockIdx.x;                 // (b, c, half)
    int half = bid & 1;
    int c    = (bid >> 1) & (C_ - 1);
    int b    = bid >> 8;
    int t    = threadIdx.x;

    // Stage this channel's tables once.
    {
        const uint4* ts = g_tab8 + (size_t)c * TABW;
        const float* fs = g_tab1 + (size_t)c * TABW;
        #pragma unroll
        for (int i = t; i < TABW; i += NTHR) {
            tab8[i] = ts[i];
            tab1[i] = fs[i];
        }
    }
    __syncthreads();

    int warp = t >> 5;
    int lane = t & 31;
    bool act = lane < 28;
    int col  = 4 * lane;
    int rb   = half * HROWS + warp * 14;   // 4 warps x 14 rows = 56 per block

    const float* xp = x + ((size_t)(b * C_ + c)) * (HH * WW);
    float* obase    = out + ((size_t)(b * C_ + c)) * (HH * WW);

    uint32_t padx, pady, padw;             // zero-pixel entry words (uniform)
    { uint4 gp = tab8[255]; padx = gp.x; pady = gp.y; padw = gp.w; }

    float4 a0 = make_float4(0.f, 0.f, 0.f, 0.f);
    float4 a1 = make_float4(0.f, 0.f, 0.f, 0.f);
    float4 a2 = make_float4(0.f, 0.f, 0.f, 0.f);

    // Peel z = rb-1: a0 = P0(rb-1) (A[rb]); a2 collects junk.
    proc_row(tab8, tab1, padx, pady, padw, lane,
             ldrow(xp, rb - 1, col, act), a2, a2, a0);

    float4 fnext = ldrow(xp, rb, col, act);

    // Peel z = rb: a0 += P1(rb) -> A[rb]; a1 = P0(rb) -> A[rb+1]; junk in a2.
    {
        float4 fc = fnext;
        fnext = ldrow(xp, rb + 1, col, act);
        proc_row(tab8, tab1, padx, pady, padw, lane, fc, a2, a0, a1);
    }
    a2 = make_float4(0.f, 0.f, 0.f, 0.f);

    float* op = obase + rb * WW + col;

    #pragma unroll
    for (int i = 0; i < 14; i++) {
        // z = rb+1+i arrives; completes and emits out row rb+i (in a0).
        float4 fc = fnext;
        fnext = ldrow(xp, rb + 2 + i, col, act);
        proc_row(tab8, tab1, padx, pady, padw, lane, fc, a0, a1, a2);

        if (act)
            *(float4*)op = a0;
        op += WW;

        a0 = a1;       // out row rb+i+1 partial (P0+P1 accumulated)
        a1 = a2;       // out row rb+i+2 partial (P0 only)
        // a2 is overwritten as accN next iteration.
    }
}

extern "C" void kernel_launch(void* const* d_in, const int* in_sizes, int n_in,
                              void* d_out, int out_size) {
    const float* x      = (const float*)d_in[0];
    const float* weight = (const float*)d_in[1];
    const float* lut    = (const float*)d_in[2];
    float* out          = (float*)d_out;

    build_table_kernel<<<C_, TABW>>>(weight, lut);
    conv_kernel<<<BATCH * C_ * 2, NTHR>>>(x, out);
}

// round 16
// speedup vs baseline: 1.5506x; 1.1915x over previous
#include <cuda_runtime.h>
#include <cuda_fp16.h>
#include <stdint.h>

#define C_     128
#define HH     112
#define WW     112
#define BATCH  8
#define TABW   512            // 511 valid entries + 1 pad (255 = zero-pixel)
#define NTHR   64             // 2 warps; warp = 28 out rows; lane<28 = 4 cols
#define HROWS  56             // rows per block (half channel)
#define WROWS  28             // out rows per warp

// Per-channel packed tables:
// g_tab8[c*512+i] = half8 {t00,t01,t02,t10,t11,t12,t20,t21} for index i
// g_tab1[c*512+i] = float t22
__device__ uint4 g_tab8[C_ * TABW];
__device__ float g_tab1[C_ * TABW];

__global__ void build_table_kernel(const float* __restrict__ weight,
                                   const float* __restrict__ lut) {
    int c = blockIdx.x;
    int j = threadIdx.x;             // 512 threads, one entry each

    float v[9];
    #pragma unroll
    for (int k = 0; k < 9; k++) {
        float w  = weight[c * 9 + k];
        float t1 = rintf(w * 1000.0f);
        t1 = fminf(fmaxf(t1, -255.0f), 255.0f);
        int   i1 = (int)fabsf(t1);
        float s1 = (t1 > 0.0f) ? 1.0f : ((t1 < 0.0f) ? -1.0f : 0.0f);
        float val = 0.0f;
        if (j < 511) {
            int t2 = j - 255;
            int i2 = abs(t2);
            bool pos = (s1 > 0.0f && t2 > 0) || (s1 < 0.0f && t2 < 0);
            val = lut[i1 * 256 + i2] * (pos ? 1.0f : -1.0f) * (1.0f / 1000.0f);
        }
        v[k] = val;
    }
    __half2 p0 = __floats2half2_rn(v[0], v[1]);
    __half2 p1 = __floats2half2_rn(v[2], v[3]);
    __half2 p2 = __floats2half2_rn(v[4], v[5]);
    __half2 p3 = __floats2half2_rn(v[6], v[7]);
    uint4 q;
    q.x = *reinterpret_cast<uint32_t*>(&p0);
    q.y = *reinterpret_cast<uint32_t*>(&p1);
    q.z = *reinterpret_cast<uint32_t*>(&p2);
    q.w = *reinterpret_cast<uint32_t*>(&p3);
    g_tab8[(size_t)c * TABW + j] = q;
    g_tab1[(size_t)c * TABW + j] = v[8];
}

__device__ __forceinline__ float h_lo(uint32_t u) {
    __half2 h = *reinterpret_cast<__half2*>(&u);
    return __low2float(h);
}
__device__ __forceinline__ float h_hi(uint32_t u) {
    __half2 h = *reinterpret_cast<__half2*>(&u);
    return __high2float(h);
}

__device__ __forceinline__ float4 ldrow(const float* __restrict__ xp, int r, int col, bool act) {
    if (act && r >= 0 && r < HH)
        return *(const float4*)(xp + r * WW + col);
    return make_float4(0.0f, 0.0f, 0.0f, 0.0f);
}

// One idx row z, fused into the 3-slot accumulator ring:
//   accO += P2(z)   (out row z-1, completes)
//   accM += P1(z)   (out row z)
//   accN  = P0(z)   (out row z+1, fresh)
__device__ __forceinline__ void proc_row(const uint4* __restrict__ tab8,
                                         const float* __restrict__ tab1,
                                         uint32_t padx, uint32_t pady, uint32_t padw,
                                         int lane, float4 f,
                                         float4& accO, float4& accM, float4& accN) {
    int i0 = min(max(__float2int_rn(f.x), -255), 255) + 255;
    int i1 = min(max(__float2int_rn(f.y), -255), 255) + 255;
    int i2 = min(max(__float2int_rn(f.z), -255), 255) + 255;
    int i3 = min(max(__float2int_rn(f.w), -255), 255) + 255;

    // Right-halo index for the t22 scalar gather (lane 28 holds pad idx 255).
    uint32_t hr = (uint32_t)__shfl_down_sync(0xffffffffu, i0, 1);

    uint4 g1 = tab8[i0], g2 = tab8[i1], g3 = tab8[i2], g4 = tab8[i3];
    float f0 = tab1[i1], f1 = tab1[i2], f2 = tab1[i3], f3 = tab1[hr];

    // Left halo entry g0 = left lane's g4 (3 words needed).
    uint32_t s4x = __shfl_up_sync(0xffffffffu, g4.x, 1);
    uint32_t s4y = __shfl_up_sync(0xffffffffu, g4.y, 1);
    uint32_t s4w = __shfl_up_sync(0xffffffffu, g4.w, 1);
    if (lane == 0) { s4x = padx; s4y = pady; s4w = padw; }
    // Right halo entry g5 = right lane's g1 (2 words needed).
    uint32_t s1y = __shfl_down_sync(0xffffffffu, g1.y, 1);
    uint32_t s1z = __shfl_down_sync(0xffffffffu, g1.z, 1);
    // lane 27 receives lane 28's pad gathers (idx 255). OK.

    accO.x += h_lo(s4w)  + h_hi(g1.w) + f0;
    accO.y += h_lo(g1.w) + h_hi(g2.w) + f1;
    accO.z += h_lo(g2.w) + h_hi(g3.w) + f2;
    accO.w += h_lo(g3.w) + h_hi(g4.w) + f3;

    accM.x += h_hi(s4y)  + h_lo(g1.z) + h_hi(g2.z);
    accM.y += h_hi(g1.y) + h_lo(g2.z) + h_hi(g3.z);
    accM.z += h_hi(g2.y) + h_lo(g3.z) + h_hi(g4.z);
    accM.w += h_hi(g3.y) + h_lo(g4.z) + h_hi(s1z);

    accN.x = h_lo(s4x)  + h_hi(g1.x) + h_lo(g2.y);
    accN.y = h_lo(g1.x) + h_hi(g2.x) + h_lo(g3.y);
    accN.z = h_lo(g2.x) + h_hi(g3.x) + h_lo(g4.y);
    accN.w = h_lo(g3.x) + h_hi(g4.x) + h_lo(s1y);
}

__global__ __launch_bounds__(NTHR, 20) void conv_kernel(const float* __restrict__ x,
                                                        float* __restrict__ out) {
    __shared__ uint4 tab8[TABW];                 // 8192 B
    __shared__ float tab1[TABW];                 // 2048 B

    int bid  = blockIdx.x;                 // (b, c, half)
    int half = bid & 1;
    int c    = (bid >> 1) & (C_ - 1);
    int b    = bid >> 8;
    int t    = threadIdx.x;

    // Stage this channel's tables once.
    {
        const uint4* ts = g_tab8 + (size_t)c * TABW;
        const float* fs = g_tab1 + (size_t)c * TABW;
        #pragma unroll
        for (int i = t; i < TABW; i += NTHR) {
            tab8[i] = ts[i];
            tab1[i] = fs[i];
        }
    }
    __syncthreads();

    int warp = t >> 5;
    int lane = t & 31;
    bool act = lane < 28;
    int col  = 4 * lane;
    int rb   = half * HROWS + warp * WROWS;   // 2 warps x 28 rows = 56 per block

    const float* xp = x + ((size_t)(b * C_ + c)) * (HH * WW);
    float* obase    = out + ((size_t)(b * C_ + c)) * (HH * WW);

    uint32_t padx, pady, padw;             // zero-pixel entry words (uniform)
    { uint4 gp = tab8[255]; padx = gp.x; pady = gp.y; padw = gp.w; }

    float4 a0 = make_float4(0.f, 0.f, 0.f, 0.f);
    float4 a1 = make_float4(0.f, 0.f, 0.f, 0.f);
    float4 a2 = make_float4(0.f, 0.f, 0.f, 0.f);

    // Peel z = rb-1: a0 = P0(rb-1); junk in a2.
    proc_row(tab8, tab1, padx, pady, padw, lane,
             ldrow(xp, rb - 1, col, act), a2, a2, a0);

    float4 fnext = ldrow(xp, rb, col, act);

    // Peel z = rb: a0 += P1(rb); a1 = P0(rb); junk in a2.
    {
        float4 fc = fnext;
        fnext = ldrow(xp, rb + 1, col, act);
        proc_row(tab8, tab1, padx, pady, padw, lane, fc, a2, a0, a1);
    }
    a2 = make_float4(0.f, 0.f, 0.f, 0.f);

    float* op = obase + rb * WW + col;

    #pragma unroll 4
    for (int i = 0; i < WROWS; i++) {
        // z = rb+1+i arrives; completes and emits out row rb+i (in a0).
        float4 fc = fnext;
        fnext = ldrow(xp, rb + 2 + i, col, act);
        proc_row(tab8, tab1, padx, pady, padw, lane, fc, a0, a1, a2);

        if (act)
            *(float4*)op = a0;
        op += WW;

        a0 = a1;       // out row rb+i+1 partial (P0+P1 accumulated)
        a1 = a2;       // out row rb+i+2 partial (P0 only)
        // a2 is overwritten as accN next iteration.
    }
}

extern "C" void kernel_launch(void* const* d_in, const int* in_sizes, int n_in,
                              void* d_out, int out_size) {
    const float* x      = (const float*)d_in[0];
    const float* weight = (const float*)d_in[1];
    const float* lut    = (const float*)d_in[2];
    float* out          = (float*)d_out;

    build_table_kernel<<<C_, TABW>>>(weight, lut);
    conv_kernel<<<BATCH * C_ * 2, NTHR>>>(x, out);
}

// round 17
// speedup vs baseline: 1.7104x; 1.1031x over previous
#include <cuda_runtime.h>
#include <cuda_fp16.h>
#include <stdint.h>

#define C_     128
#define HH     112
#define WW     112
#define BATCH  8
#define TABW   512            // 511 valid entries + 1 pad (255 = zero-pixel)
#define NTHR   64             // 2 warps; warp = 28 out rows; lane<28 = 4 cols
#define HROWS  56             // rows per block (half channel)
#define WROWS  28             // out rows per warp

// Per-channel packed tables:
// g_tab8[c*512+i] = half8 {t00,t01,t02,t10,t11,t12,t20,t21} for index i
// g_tab1[c*512+i] = float t22
__device__ uint4 g_tab8[C_ * TABW];
__device__ float g_tab1[C_ * TABW];

__global__ void build_table_kernel(const float* __restrict__ weight,
                                   const float* __restrict__ lut) {
    int c = blockIdx.x;
    int j = threadIdx.x;             // 512 threads, one entry each

    float v[9];
    #pragma unroll
    for (int k = 0; k < 9; k++) {
        float w  = weight[c * 9 + k];
        float t1 = rintf(w * 1000.0f);
        t1 = fminf(fmaxf(t1, -255.0f), 255.0f);
        int   i1 = (int)fabsf(t1);
        float s1 = (t1 > 0.0f) ? 1.0f : ((t1 < 0.0f) ? -1.0f : 0.0f);
        float val = 0.0f;
        if (j < 511) {
            int t2 = j - 255;
            int i2 = abs(t2);
            bool pos = (s1 > 0.0f && t2 > 0) || (s1 < 0.0f && t2 < 0);
            val = lut[i1 * 256 + i2] * (pos ? 1.0f : -1.0f) * (1.0f / 1000.0f);
        }
        v[k] = val;
    }
    __half2 p0 = __floats2half2_rn(v[0], v[1]);
    __half2 p1 = __floats2half2_rn(v[2], v[3]);
    __half2 p2 = __floats2half2_rn(v[4], v[5]);
    __half2 p3 = __floats2half2_rn(v[6], v[7]);
    uint4 q;
    q.x = *reinterpret_cast<uint32_t*>(&p0);
    q.y = *reinterpret_cast<uint32_t*>(&p1);
    q.z = *reinterpret_cast<uint32_t*>(&p2);
    q.w = *reinterpret_cast<uint32_t*>(&p3);
    g_tab8[(size_t)c * TABW + j] = q;
    g_tab1[(size_t)c * TABW + j] = v[8];
}

__device__ __forceinline__ float h_lo(uint32_t u) {
    __half2 h = *reinterpret_cast<__half2*>(&u);
    return __low2float(h);
}
__device__ __forceinline__ float h_hi(uint32_t u) {
    __half2 h = *reinterpret_cast<__half2*>(&u);
    return __high2float(h);
}

__device__ __forceinline__ float4 ldrow(const float* __restrict__ xp, int r, int col, bool act) {
    if (act && r >= 0 && r < HH)
        return *(const float4*)(xp + r * WW + col);
    return make_float4(0.0f, 0.0f, 0.0f, 0.0f);
}

// All loaded/shuffled material for one idx row.
struct Gath {
    uint4 g1, g2, g3, g4;
    uint32_t s4x, s4y, s4w, s1y, s1z;
    float f0, f1, f2, f3;
};

__device__ __forceinline__ Gath gather_row(const uint4* __restrict__ tab8,
                                           const float* __restrict__ tab1,
                                           uint32_t padx, uint32_t pady, uint32_t padw,
                                           int lane, float4 f) {
    Gath G;
    int i0 = min(max(__float2int_rn(f.x), -255), 255) + 255;
    int i1 = min(max(__float2int_rn(f.y), -255), 255) + 255;
    int i2 = min(max(__float2int_rn(f.z), -255), 255) + 255;
    int i3 = min(max(__float2int_rn(f.w), -255), 255) + 255;

    uint32_t hr = (uint32_t)__shfl_down_sync(0xffffffffu, i0, 1);

    G.g1 = tab8[i0]; G.g2 = tab8[i1]; G.g3 = tab8[i2]; G.g4 = tab8[i3];
    G.f0 = tab1[i1]; G.f1 = tab1[i2]; G.f2 = tab1[i3]; G.f3 = tab1[hr];

    G.s4x = __shfl_up_sync(0xffffffffu, G.g4.x, 1);
    G.s4y = __shfl_up_sync(0xffffffffu, G.g4.y, 1);
    G.s4w = __shfl_up_sync(0xffffffffu, G.g4.w, 1);
    if (lane == 0) { G.s4x = padx; G.s4y = pady; G.s4w = padw; }
    G.s1y = __shfl_down_sync(0xffffffffu, G.g1.y, 1);
    G.s1z = __shfl_down_sync(0xffffffffu, G.g1.z, 1);
    return G;
}

__device__ __forceinline__ float4 P0of(const Gath& G) {
    return make_float4(h_lo(G.s4x)  + h_hi(G.g1.x) + h_lo(G.g2.y),
                       h_lo(G.g1.x) + h_hi(G.g2.x) + h_lo(G.g3.y),
                       h_lo(G.g2.x) + h_hi(G.g3.x) + h_lo(G.g4.y),
                       h_lo(G.g3.x) + h_hi(G.g4.x) + h_lo(G.s1y));
}
__device__ __forceinline__ float4 P1of(const Gath& G) {
    return make_float4(h_hi(G.s4y)  + h_lo(G.g1.z) + h_hi(G.g2.z),
                       h_hi(G.g1.y) + h_lo(G.g2.z) + h_hi(G.g3.z),
                       h_hi(G.g2.y) + h_lo(G.g3.z) + h_hi(G.g4.z),
                       h_hi(G.g3.y) + h_lo(G.g4.z) + h_hi(G.s1z));
}
__device__ __forceinline__ float4 P2of(const Gath& G) {
    return make_float4(h_lo(G.s4w)  + h_hi(G.g1.w) + G.f0,
                       h_lo(G.g1.w) + h_hi(G.g2.w) + G.f1,
                       h_lo(G.g2.w) + h_hi(G.g3.w) + G.f2,
                       h_lo(G.g3.w) + h_hi(G.g4.w) + G.f3);
}

__device__ __forceinline__ float4 add4(float4 a, float4 b) {
    return make_float4(a.x + b.x, a.y + b.y, a.z + b.z, a.w + b.w);
}

__global__ __launch_bounds__(NTHR, 14) void conv_kernel(const float* __restrict__ x,
                                                        float* __restrict__ out) {
    __shared__ uint4 tab8[TABW];                 // 8192 B
    __shared__ float tab1[TABW];                 // 2048 B

    int bid  = blockIdx.x;                 // (b, c, half)
    int half = bid & 1;
    int c    = (bid >> 1) & (C_ - 1);
    int b    = bid >> 8;
    int t    = threadIdx.x;

    // Stage this channel's tables once.
    {
        const uint4* ts = g_tab8 + (size_t)c * TABW;
        const float* fs = g_tab1 + (size_t)c * TABW;
        #pragma unroll
        for (int i = t; i < TABW; i += NTHR) {
            tab8[i] = ts[i];
            tab1[i] = fs[i];
        }
    }
    __syncthreads();

    int warp = t >> 5;
    int lane = t & 31;
    bool act = lane < 28;
    int col  = 4 * lane;
    int rb   = half * HROWS + warp * WROWS;   // 2 warps x 28 rows = 56 per block

    const float* xp = x + ((size_t)(b * C_ + c)) * (HH * WW);
    float* obase    = out + ((size_t)(b * C_ + c)) * (HH * WW);

    uint32_t padx, pady, padw;             // zero-pixel entry words (uniform)
    { uint4 gp = tab8[255]; padx = gp.x; pady = gp.y; padw = gp.w; }

    // State entering the loop: a0 = partial of out row rb (P0(rb-1)+P1(rb)),
    //                          a1 = partial of out row rb+1 (P0(rb)).
    float4 a0, a1;
    {
        Gath Gm = gather_row(tab8, tab1, padx, pady, padw, lane,
                             ldrow(xp, rb - 1, col, act));
        Gath Gz = gather_row(tab8, tab1, padx, pady, padw, lane,
                             ldrow(xp, rb, col, act));
        a0 = add4(P0of(Gm), P1of(Gz));
        a1 = P0of(Gz);
    }

    float4 fA = ldrow(xp, rb + 1, col, act);
    float4 fB = ldrow(xp, rb + 2, col, act);

    float* op = obase + rb * WW + col;

    #pragma unroll
    for (int i = 0; i < WROWS / 2; i++) {
        // idx rows z1 = rb+1+2i, z2 = z1+1; emit out rows rb+2i, rb+2i+1.
        float4 f1 = fA, f2 = fB;
        fA = ldrow(xp, rb + 3 + 2 * i, col, act);
        fB = ldrow(xp, rb + 4 + 2 * i, col, act);

        Gath GA = gather_row(tab8, tab1, padx, pady, padw, lane, f1);
        Gath GB = gather_row(tab8, tab1, padx, pady, padw, lane, f2);

        // Accumulate A while B's LDS are still in flight.
        float4 o0 = add4(a0, P2of(GA));
        if (act) *(float4*)op = o0;
        float4 n0 = add4(a1, P1of(GA));
        float4 n1 = P0of(GA);

        float4 o1 = add4(n0, P2of(GB));
        if (act) *(float4*)(op + WW) = o1;
        a0 = add4(n1, P1of(GB));
        a1 = P0of(GB);

        op += 2 * WW;
    }
}

extern "C" void kernel_launch(void* const* d_in, const int* in_sizes, int n_in,
                              void* d_out, int out_size) {
    const float* x      = (const float*)d_in[0];
    const float* weight = (const float*)d_in[1];
    const float* lut    = (const float*)d_in[2];
    float* out          = (float*)d_out;

    build_table_kernel<<<C_, TABW>>>(weight, lut);
    conv_kernel<<<BATCH * C_ * 2, NTHR>>>(x, out);
}